// round 13
// baseline (speedup 1.0000x reference)
#include <cuda_runtime.h>
#include <cuda_bf16.h>
#include <cstdint>

#define NN 50000
#define EE 800000
#define KF 256          // IN_FEATS
#define HH 4
#define HD 128          // H*D
#define NH 200000       // N*H
#define MTILE 64
#define KC 64           // K chunk
#define NCHUNK (KF / KC)
#define NSCB 196        // scan blocks = ceil(NN/256)

// gemm smem: A stages 2 x (hi8K+lo8K) = 32KB ; B stages 2 x (hi16K+lo16K) = 64KB
#define A_STG_SIZE 16384
#define B_BASE_OFF 32768
#define B_STG_SIZE 32768

// ---------------- scratch (device globals; no allocation) ----------------
__device__ float g_ft[NN * HD];
__device__ float g_el[NH];
__device__ float g_er[NH];
__device__ int   g_srcs[EE];         // src node ids, CSR-sorted by dst
__device__ int   g_deg[NN];
__device__ int   g_rank[EE];         // rank of edge within its dst segment
__device__ int   g_rowstart[NN + 1];
__device__ int   g_bsum[NSCB];
__device__ int   g_boff[NSCB];
__device__ __nv_bfloat16 g_wt_hi[HD * KF];   // W^T split-high  [n][k]
__device__ __nv_bfloat16 g_wt_lo[HD * KF];   // W^T split-low   [n][k]

// ---------------- helpers ----------------
__device__ __forceinline__ uint32_t smem_u32(const void* p) {
    uint32_t a;
    asm("{ .reg .u64 t; cvta.to.shared.u64 t, %1; cvt.u32.u64 %0, t; }" : "=r"(a) : "l"(p));
    return a;
}

#define SW128(o) ((o) ^ (((o) >> 3) & 0x70))

__device__ __forceinline__ void ldm_x4(uint32_t* r, uint32_t addr) {
    asm volatile("ldmatrix.sync.aligned.m8n8.x4.shared.b16 {%0,%1,%2,%3}, [%4];"
                 : "=r"(r[0]), "=r"(r[1]), "=r"(r[2]), "=r"(r[3]) : "r"(addr));
}

__device__ __forceinline__ void mma16816(float* c, const uint32_t* a, const uint32_t* b) {
    asm volatile(
        "mma.sync.aligned.m16n8k16.row.col.f32.bf16.bf16.f32 "
        "{%0,%1,%2,%3}, {%4,%5,%6,%7}, {%8,%9}, {%0,%1,%2,%3};"
        : "+f"(c[0]), "+f"(c[1]), "+f"(c[2]), "+f"(c[3])
        : "r"(a[0]), "r"(a[1]), "r"(a[2]), "r"(a[3]), "r"(b[0]), "r"(b[1]));
}

__device__ __forceinline__ void split_bf16(float x, unsigned short& h, unsigned short& l) {
    __nv_bfloat16 bh = __float2bfloat16(x);
    float r = x - __bfloat162float(bh);
    __nv_bfloat16 bl = __float2bfloat16(r);
    h = __bfloat16_as_ushort(bh);
    l = __bfloat16_as_ushort(bl);
}

// ---------------- setup: zero deg + W transpose/split (merged) ----------------
__global__ void setup_kernel(const float* __restrict__ W) {
    int i = blockIdx.x * 256 + threadIdx.x;
    if (i < NN) g_deg[i] = 0;
    if (i < HD * KF) {
        int n = i >> 8;
        int k = i & 255;
        float w = W[k * HD + n];
        unsigned short h, l;
        split_bf16(w, h, l);
        g_wt_hi[n * KF + k] = __ushort_as_bfloat16(h);
        g_wt_lo[n * KF + k] = __ushort_as_bfloat16(l);
    }
}

// ---------------- B stage fill via cp.async ----------------
__device__ __forceinline__ void issue_b(int kc, uint32_t stg, int tid) {
#pragma unroll
    for (int l = 0; l < 4; l++) {
        int q = tid + l * 256;              // 0..1023
        int row = q >> 3, c = q & 7;        // n row 0..127, 16B col
        int gidx = row * KF + kc * KC + c * 8;
        uint32_t off = SW128((uint32_t)(row * 128 + c * 16));
        asm volatile("cp.async.cg.shared.global [%0], [%1], 16;"
                     :: "r"(stg + off), "l"(&g_wt_hi[gidx]));
        asm volatile("cp.async.cg.shared.global [%0], [%1], 16;"
                     :: "r"(stg + 16384 + off), "l"(&g_wt_lo[gidx]));
    }
    asm volatile("cp.async.commit_group;" ::: "memory");
}

// ---------------- mma.sync bf16x3 GEMM: m64 CTA, A+B double-buffered, 1 sync/chunk ----------------
__global__ void __launch_bounds__(256, 2) gemm_kernel(const float* __restrict__ A,
                                                      const float* __restrict__ attn_l,
                                                      const float* __restrict__ attn_r) {
    extern __shared__ char smem[];
    const uint32_t sbase = smem_u32(smem);
    const uint32_t ubase = (sbase + 1023) & ~1023u;

    const int tid = threadIdx.x;
    const int wid = tid >> 5;
    const int lane = tid & 31;
    const int wm = wid & 3;        // 4 m groups of 16 rows
    const int wn = wid >> 2;       // 2 n groups of 64 cols
    const int block_row = blockIdx.x * MTILE;

    const int lrow = (lane & 7) + ((lane >> 3) & 1) * 8;
    const int lkh  = (lane >> 4) * 16;
    const int arow_base = tid >> 4;     // 0..15 (+ l*16 -> 0..63)
    const int ac4 = tid & 15;

    // ---- prologue: B0 in flight, A0 loaded + split into stage 0 ----
    issue_b(0, ubase + B_BASE_OFF, tid);

    float4 a_cur[4];
#pragma unroll
    for (int l = 0; l < 4; l++) {
        int grow = block_row + arow_base + l * 16;
        a_cur[l] = (grow < NN) ? *(const float4*)&A[grow * KF + ac4 * 4]
                               : make_float4(0.f, 0.f, 0.f, 0.f);
    }
#pragma unroll
    for (int l = 0; l < 4; l++) {
        int row = arow_base + l * 16;
        float4 v = a_cur[l];
        unsigned short h0, h1, h2, h3, l0, l1, l2, l3;
        split_bf16(v.x, h0, l0); split_bf16(v.y, h1, l1);
        split_bf16(v.z, h2, l2); split_bf16(v.w, h3, l3);
        uint32_t off = SW128((uint32_t)(row * 128 + ac4 * 8));
        *(uint2*)(smem + (ubase - sbase) + off) =
            make_uint2(((uint32_t)h1 << 16) | h0, ((uint32_t)h3 << 16) | h2);
        *(uint2*)(smem + (ubase - sbase) + 8192 + off) =
            make_uint2(((uint32_t)l1 << 16) | l0, ((uint32_t)l3 << 16) | l2);
    }

    float acc[8][4];
#pragma unroll
    for (int j = 0; j < 8; j++)
#pragma unroll
        for (int q = 0; q < 4; q++) acc[j][q] = 0.0f;

    for (int kc = 0; kc < NCHUNK; kc++) {
        // LDG next A chunk early (hides under wait+sync+split)
        float4 a_nxt[4];
        if (kc + 1 < NCHUNK) {
#pragma unroll
            for (int l = 0; l < 4; l++) {
                int grow = block_row + arow_base + l * 16;
                a_nxt[l] = (grow < NN)
                    ? *(const float4*)&A[grow * KF + (kc + 1) * KC + ac4 * 4]
                    : make_float4(0.f, 0.f, 0.f, 0.f);
            }
        }
        asm volatile("cp.async.wait_group 0;" ::: "memory");
        __syncthreads();    // A[kc] stores + B[kc] arrival visible block-wide

        if (kc + 1 < NCHUNK) {
            issue_b(kc + 1, ubase + B_BASE_OFF + ((kc + 1) & 1) * B_STG_SIZE, tid);
            // split next A into the other stage (readers of it finished pre-sync)
            uint32_t astg = (ubase - sbase) + ((kc + 1) & 1) * A_STG_SIZE;
#pragma unroll
            for (int l = 0; l < 4; l++) {
                int row = arow_base + l * 16;
                float4 v = a_nxt[l];
                unsigned short h0, h1, h2, h3, l0, l1, l2, l3;
                split_bf16(v.x, h0, l0); split_bf16(v.y, h1, l1);
                split_bf16(v.z, h2, l2); split_bf16(v.w, h3, l3);
                uint32_t off = SW128((uint32_t)(row * 128 + ac4 * 8));
                *(uint2*)(smem + astg + off) =
                    make_uint2(((uint32_t)h1 << 16) | h0, ((uint32_t)h3 << 16) | h2);
                *(uint2*)(smem + astg + 8192 + off) =
                    make_uint2(((uint32_t)l1 << 16) | l0, ((uint32_t)l3 << 16) | l2);
            }
        }

        const uint32_t uA_hi = ubase + (kc & 1) * A_STG_SIZE;
        const uint32_t uA_lo = uA_hi + 8192;
        const uint32_t uB_hi = ubase + B_BASE_OFF + (kc & 1) * B_STG_SIZE;
        const uint32_t uB_lo = uB_hi + 16384;
#pragma unroll
        for (int ks = 0; ks < 4; ks++) {
            const int kb = ks * 32;

            uint32_t ah[4], al[4];
            int arow = wm * 16 + lrow;
            uint32_t aoff = SW128((uint32_t)(arow * 128 + kb + lkh));
            ldm_x4(ah, uA_hi + aoff);
            ldm_x4(al, uA_lo + aoff);

#pragma unroll
            for (int np = 0; np < 4; np++) {
                int brow = wn * 64 + np * 16 + ((lane >> 4) * 8) + (lane & 7);
                uint32_t boff = SW128((uint32_t)(brow * 128 + kb + (((lane >> 3) & 1) * 16)));
                uint32_t bh[4], bl[4];
                ldm_x4(bh, uB_hi + boff);
                mma16816(acc[np * 2 + 0], ah, bh + 0);
                mma16816(acc[np * 2 + 1], ah, bh + 2);
                mma16816(acc[np * 2 + 0], al, bh + 0);
                mma16816(acc[np * 2 + 1], al, bh + 2);
                ldm_x4(bl, uB_lo + boff);
                mma16816(acc[np * 2 + 0], ah, bl + 0);
                mma16816(acc[np * 2 + 1], ah, bl + 2);
            }
        }
    }

    // --- epilogue: store g_ft + fused el/er (registers only; no sync needed) ---
    const int qrow = lane >> 2;          // 0..7
    const int qcol = (lane & 3) * 2;
    float elp[2][2], erp[2][2];
#pragma unroll
    for (int i = 0; i < 2; i++) { elp[i][0] = elp[i][1] = 0.f; erp[i][0] = erp[i][1] = 0.f; }

#pragma unroll
    for (int nt = 0; nt < 8; nt++) {
        int col = wn * 64 + nt * 8 + qcol;
        int hloc = nt >> 2;
        float wl0 = attn_l[col], wl1 = attn_l[col + 1];
        float wr0 = attn_r[col], wr1 = attn_r[col + 1];
        int r0 = block_row + wm * 16 + qrow;
        float c0 = acc[nt][0], c1 = acc[nt][1], c2 = acc[nt][2], c3 = acc[nt][3];
        if (r0 < NN) *(float2*)&g_ft[r0 * HD + col] = make_float2(c0, c1);
        if (r0 + 8 < NN) *(float2*)&g_ft[(r0 + 8) * HD + col] = make_float2(c2, c3);
        elp[0][hloc] += c0 * wl0 + c1 * wl1;
        erp[0][hloc] += c0 * wr0 + c1 * wr1;
        elp[1][hloc] += c2 * wl0 + c3 * wl1;
        erp[1][hloc] += c2 * wr0 + c3 * wr1;
    }
#pragma unroll
    for (int o = 1; o <= 2; o <<= 1) {
#pragma unroll
        for (int i = 0; i < 2; i++) {
#pragma unroll
            for (int hl = 0; hl < 2; hl++) {
                elp[i][hl] += __shfl_xor_sync(0xffffffffu, elp[i][hl], o);
                erp[i][hl] += __shfl_xor_sync(0xffffffffu, erp[i][hl], o);
            }
        }
    }
    if ((lane & 3) == 0) {
        int hbase = wn * 2;
#pragma unroll
        for (int rh = 0; rh < 2; rh++) {
            int n = block_row + wm * 16 + qrow + rh * 8;
            if (n < NN) {
                g_el[n * HH + hbase]     = elp[rh][0];
                g_er[n * HH + hbase]     = erp[rh][0];
                g_el[n * HH + hbase + 1] = elp[rh][1];
                g_er[n * HH + hbase + 1] = erp[rh][1];
            }
        }
    }
}

// ---------------- degree histogram: 4 edges/thread for atomic MLP ----------------
__global__ void hist_kernel(const int* __restrict__ dst) {
    int base = blockIdx.x * 1024 + threadIdx.x;
#pragma unroll
    for (int l = 0; l < 4; l++) {
        int e = base + l * 256;
        if (e < EE) g_rank[e] = atomicAdd(&g_deg[dst[e]], 1);
    }
}

// ---------------- hierarchical scan: 3 small wide kernels ----------------
__global__ void scan1_kernel() {
    __shared__ int sh[256];
    int t = threadIdx.x;
    int idx = blockIdx.x * 256 + t;
    int v = (idx < NN) ? g_deg[idx] : 0;
    sh[t] = v;
    __syncthreads();
#pragma unroll
    for (int d = 1; d < 256; d <<= 1) {
        int a = (t >= d) ? sh[t - d] : 0;
        __syncthreads();
        sh[t] += a;
        __syncthreads();
    }
    if (idx < NN) g_rowstart[idx] = sh[t] - v;
    if (t == 255) g_bsum[blockIdx.x] = sh[255];
}

__global__ void scan2_kernel() {
    __shared__ int sh[256];
    int t = threadIdx.x;
    int v = (t < NSCB) ? g_bsum[t] : 0;
    sh[t] = v;
    __syncthreads();
#pragma unroll
    for (int d = 1; d < 256; d <<= 1) {
        int a = (t >= d) ? sh[t - d] : 0;
        __syncthreads();
        sh[t] += a;
        __syncthreads();
    }
    if (t < NSCB) g_boff[t] = sh[t] - v;
}

__global__ void scan3_kernel() {
    int idx = blockIdx.x * 256 + threadIdx.x;
    if (idx < NN) g_rowstart[idx] += g_boff[blockIdx.x];
    if (idx == 0) g_rowstart[NN] = EE;
}

// ---------------- scatter src ids into CSR order (atomic-free) ----------------
__global__ void sced_kernel(const int* __restrict__ src, const int* __restrict__ dst) {
    int e = blockIdx.x * blockDim.x + threadIdx.x;
    if (e >= EE) return;
    g_srcs[g_rowstart[dst[e]] + g_rank[e]] = src[e];
}

// ---------------- SpMM: dst-centric, fused edge softmax, atomic-free ----------------
__global__ void spmm_kernel(float* __restrict__ out, const float* __restrict__ bias) {
    int n = blockIdx.x;
    int h = threadIdx.x >> 5;
    int lane = threadIdx.x & 31;
    int rs = g_rowstart[n], re = g_rowstart[n + 1];
    int off = h * 32 + lane;
    float er_h = g_er[n * HH + h];
    float acc = 0.f;
    float ssum = 0.f;
    for (int base = rs; base < re; base += 32) {
        int cnt = re - base;
        if (cnt > 32) cnt = 32;
        int sn = 0;
        float av = 0.f;
        if (lane < cnt) {
            sn = g_srcs[base + lane];
            float x = g_el[sn * HH + h] + er_h;
            x = (x > 0.f) ? x : 0.2f * x;
            av = __expf(x);
        }
        for (int j0 = 0; j0 < cnt; j0 += 8) {
#pragma unroll
            for (int jj = 0; jj < 8; jj++) {
                int j = j0 + jj;
                int snj = __shfl_sync(0xffffffffu, sn, j);
                float aj = __shfl_sync(0xffffffffu, av, j);
                acc += g_ft[snj * HD + off] * aj;   // aj==0 past cnt
                ssum += aj;
            }
        }
    }
    float invs = (re > rs) ? (1.0f / ssum) : 0.f;
    out[n * HD + off] = acc * invs + bias[off];
}

// ---------------- launch ----------------
extern "C" void kernel_launch(void* const* d_in, const int* in_sizes, int n_in,
                              void* d_out, int out_size) {
    const float* feat   = (const float*)d_in[0];
    const int*   src    = (const int*)  d_in[1];
    const int*   dst    = (const int*)  d_in[2];
    const float* W      = (const float*)d_in[3];
    const float* attn_l = (const float*)d_in[4];
    const float* attn_r = (const float*)d_in[5];
    const float* bias   = (const float*)d_in[6];
    float* out = (float*)d_out;

    const int smem_bytes = B_BASE_OFF + 2 * B_STG_SIZE + 1024 + 64;   // ~97.3KB
    cudaFuncSetAttribute(gemm_kernel, cudaFuncAttributeMaxDynamicSharedMemorySize, smem_bytes);

    setup_kernel<<<NSCB, 256>>>(W);
    hist_kernel<<<(EE + 1023) / 1024, 256>>>(dst);
    scan1_kernel<<<NSCB, 256>>>();
    scan2_kernel<<<1, 256>>>();
    scan3_kernel<<<NSCB, 256>>>();
    gemm_kernel<<<(NN + MTILE - 1) / MTILE, 256, smem_bytes>>>(feat, attn_l, attn_r);
    sced_kernel<<<(EE + 255) / 256, 256>>>(src, dst);
    spmm_kernel<<<NN, 128>>>(out, bias);
}

// round 14
// speedup vs baseline: 1.4704x; 1.4704x over previous
#include <cuda_runtime.h>
#include <cuda_bf16.h>
#include <cstdint>

#define NN 50000
#define EE 800000
#define KF 256          // IN_FEATS
#define HH 4
#define HD 128          // H*D
#define NH 200000       // N*H
#define MTILE 64
#define KC 64           // K chunk
#define NCHUNK (KF / KC)
#define NSCB 196        // scan blocks = ceil(NN/256)

// gemm smem: A bf16 hi/lo (2x8KB) + 2-stage B hi/lo (2x32KB) = 80KB
#define A_HI_OFF 0
#define A_LO_OFF 8192
#define STG_OFF  16384
#define STG_SIZE 32768   // hi 16KB + lo 16KB

// ---------------- scratch (device globals; no allocation) ----------------
__device__ float g_ft[NN * HD];
__device__ float g_el[NH];
__device__ float g_er[NH];
__device__ int   g_srcs[EE];         // src node ids, CSR-sorted by dst
__device__ int   g_deg[NN];
__device__ int   g_rank[EE];         // rank of edge within its dst segment
__device__ int   g_rowstart[NN + 1];
__device__ int   g_bsum[NSCB];
__device__ int   g_boff[NSCB];
__device__ __nv_bfloat16 g_wt_hi[HD * KF];   // W^T split-high  [n][k]
__device__ __nv_bfloat16 g_wt_lo[HD * KF];   // W^T split-low   [n][k]

// ---------------- helpers ----------------
__device__ __forceinline__ uint32_t smem_u32(const void* p) {
    uint32_t a;
    asm("{ .reg .u64 t; cvta.to.shared.u64 t, %1; cvt.u32.u64 %0, t; }" : "=r"(a) : "l"(p));
    return a;
}

#define SW128(o) ((o) ^ (((o) >> 3) & 0x70))

__device__ __forceinline__ void ldm_x4(uint32_t* r, uint32_t addr) {
    asm volatile("ldmatrix.sync.aligned.m8n8.x4.shared.b16 {%0,%1,%2,%3}, [%4];"
                 : "=r"(r[0]), "=r"(r[1]), "=r"(r[2]), "=r"(r[3]) : "r"(addr));
}

__device__ __forceinline__ void mma16816(float* c, const uint32_t* a, const uint32_t* b) {
    asm volatile(
        "mma.sync.aligned.m16n8k16.row.col.f32.bf16.bf16.f32 "
        "{%0,%1,%2,%3}, {%4,%5,%6,%7}, {%8,%9}, {%0,%1,%2,%3};"
        : "+f"(c[0]), "+f"(c[1]), "+f"(c[2]), "+f"(c[3])
        : "r"(a[0]), "r"(a[1]), "r"(a[2]), "r"(a[3]), "r"(b[0]), "r"(b[1]));
}

__device__ __forceinline__ void split_bf16(float x, unsigned short& h, unsigned short& l) {
    __nv_bfloat16 bh = __float2bfloat16(x);
    float r = x - __bfloat162float(bh);
    __nv_bfloat16 bl = __float2bfloat16(r);
    h = __bfloat16_as_ushort(bh);
    l = __bfloat16_as_ushort(bl);
}

// ---------------- setup: zero deg + W transpose/split (merged) ----------------
__global__ void setup_kernel(const float* __restrict__ W) {
    int i = blockIdx.x * 256 + threadIdx.x;
    if (i < NN) g_deg[i] = 0;
    if (i < HD * KF) {
        int n = i >> 8;
        int k = i & 255;
        float w = W[k * HD + n];
        unsigned short h, l;
        split_bf16(w, h, l);
        g_wt_hi[n * KF + k] = __ushort_as_bfloat16(h);
        g_wt_lo[n * KF + k] = __ushort_as_bfloat16(l);
    }
}

// ---------------- B stage fill via cp.async ----------------
__device__ __forceinline__ void issue_b(int kc, uint32_t stg, int tid) {
#pragma unroll
    for (int l = 0; l < 4; l++) {
        int q = tid + l * 256;              // 0..1023
        int row = q >> 3, c = q & 7;        // n row 0..127, 16B col
        int gidx = row * KF + kc * KC + c * 8;
        uint32_t off = SW128((uint32_t)(row * 128 + c * 16));
        asm volatile("cp.async.cg.shared.global [%0], [%1], 16;"
                     :: "r"(stg + off), "l"(&g_wt_hi[gidx]));
        asm volatile("cp.async.cg.shared.global [%0], [%1], 16;"
                     :: "r"(stg + 16384 + off), "l"(&g_wt_lo[gidx]));
    }
    asm volatile("cp.async.commit_group;" ::: "memory");
}

// ---------------- mma.sync bf16x3 GEMM: m64 CTA, 2 CTA/SM (R12-proven structure) ----------------
__global__ void __launch_bounds__(256, 2) gemm_kernel(const float* __restrict__ A,
                                                      const float* __restrict__ attn_l,
                                                      const float* __restrict__ attn_r) {
    extern __shared__ char smem[];
    const uint32_t sbase = smem_u32(smem);
    const uint32_t ubase = (sbase + 1023) & ~1023u;
    const uint32_t uA_hi = ubase + A_HI_OFF;
    const uint32_t uA_lo = ubase + A_LO_OFF;

    const int tid = threadIdx.x;
    const int wid = tid >> 5;
    const int lane = tid & 31;
    const int wm = wid & 3;        // 4 m groups of 16 rows
    const int wn = wid >> 2;       // 2 n groups of 64 cols
    const int block_row = blockIdx.x * MTILE;

    // prefetch B chunk 0
    issue_b(0, ubase + STG_OFF, tid);

    float acc[8][4];
#pragma unroll
    for (int j = 0; j < 8; j++)
#pragma unroll
        for (int q = 0; q < 4; q++) acc[j][q] = 0.0f;

    const int lrow = (lane & 7) + ((lane >> 3) & 1) * 8;
    const int lkh  = (lane >> 4) * 16;
    const int arow_base = tid >> 4;     // 0..15 (+ l*16 -> 0..63)
    const int ac4 = tid & 15;

    // prefetch A chunk 0 into regs
    float4 a_cur[4];
#pragma unroll
    for (int l = 0; l < 4; l++) {
        int grow = block_row + arow_base + l * 16;
        a_cur[l] = (grow < NN) ? *(const float4*)&A[grow * KF + ac4 * 4]
                               : make_float4(0.f, 0.f, 0.f, 0.f);
    }

    for (int kc = 0; kc < NCHUNK; kc++) {
        // split current A chunk to bf16 hi/lo smem
#pragma unroll
        for (int l = 0; l < 4; l++) {
            int row = arow_base + l * 16;
            float4 v = a_cur[l];
            unsigned short h0, h1, h2, h3, l0, l1, l2, l3;
            split_bf16(v.x, h0, l0); split_bf16(v.y, h1, l1);
            split_bf16(v.z, h2, l2); split_bf16(v.w, h3, l3);
            uint32_t off = SW128((uint32_t)(row * 128 + ac4 * 8));
            *(uint2*)(smem + (uA_hi - sbase) + off) =
                make_uint2(((uint32_t)h1 << 16) | h0, ((uint32_t)h3 << 16) | h2);
            *(uint2*)(smem + (uA_lo - sbase) + off) =
                make_uint2(((uint32_t)l1 << 16) | l0, ((uint32_t)l3 << 16) | l2);
        }
        // prefetch next A chunk (regs free after split; hides under MMA loop)
        if (kc + 1 < NCHUNK) {
#pragma unroll
            for (int l = 0; l < 4; l++) {
                int grow = block_row + arow_base + l * 16;
                a_cur[l] = (grow < NN)
                    ? *(const float4*)&A[grow * KF + (kc + 1) * KC + ac4 * 4]
                    : make_float4(0.f, 0.f, 0.f, 0.f);
            }
            issue_b(kc + 1, ubase + STG_OFF + ((kc + 1) & 1) * STG_SIZE, tid);
            asm volatile("cp.async.wait_group 1;" ::: "memory");
        } else {
            asm volatile("cp.async.wait_group 0;" ::: "memory");
        }
        __syncthreads();

        const uint32_t uB_hi = ubase + STG_OFF + (kc & 1) * STG_SIZE;
        const uint32_t uB_lo = uB_hi + 16384;
#pragma unroll
        for (int ks = 0; ks < 4; ks++) {
            const int kb = ks * 32;

            uint32_t ah[4], al[4];
            int arow = wm * 16 + lrow;
            uint32_t aoff = SW128((uint32_t)(arow * 128 + kb + lkh));
            ldm_x4(ah, uA_hi + aoff);
            ldm_x4(al, uA_lo + aoff);

#pragma unroll
            for (int np = 0; np < 4; np++) {
                int brow = wn * 64 + np * 16 + ((lane >> 4) * 8) + (lane & 7);
                uint32_t boff = SW128((uint32_t)(brow * 128 + kb + (((lane >> 3) & 1) * 16)));
                uint32_t bh[4], bl[4];
                ldm_x4(bh, uB_hi + boff);
                mma16816(acc[np * 2 + 0], ah, bh + 0);
                mma16816(acc[np * 2 + 1], ah, bh + 2);
                mma16816(acc[np * 2 + 0], al, bh + 0);
                mma16816(acc[np * 2 + 1], al, bh + 2);
                ldm_x4(bl, uB_lo + boff);
                mma16816(acc[np * 2 + 0], ah, bl + 0);
                mma16816(acc[np * 2 + 1], ah, bl + 2);
            }
        }
        __syncthreads();
    }

    // --- epilogue: store g_ft + fused el/er ---
    const int qrow = lane >> 2;          // 0..7
    const int qcol = (lane & 3) * 2;
    float elp[2][2], erp[2][2];          // [row-half rh][head-local]
#pragma unroll
    for (int i = 0; i < 2; i++) { elp[i][0] = elp[i][1] = 0.f; erp[i][0] = erp[i][1] = 0.f; }

#pragma unroll
    for (int nt = 0; nt < 8; nt++) {
        int col = wn * 64 + nt * 8 + qcol;
        int hloc = nt >> 2;
        float wl0 = attn_l[col], wl1 = attn_l[col + 1];
        float wr0 = attn_r[col], wr1 = attn_r[col + 1];
        int r0 = block_row + wm * 16 + qrow;
        float c0 = acc[nt][0], c1 = acc[nt][1], c2 = acc[nt][2], c3 = acc[nt][3];
        if (r0 < NN) *(float2*)&g_ft[r0 * HD + col] = make_float2(c0, c1);
        if (r0 + 8 < NN) *(float2*)&g_ft[(r0 + 8) * HD + col] = make_float2(c2, c3);
        elp[0][hloc] += c0 * wl0 + c1 * wl1;
        erp[0][hloc] += c0 * wr0 + c1 * wr1;
        elp[1][hloc] += c2 * wl0 + c3 * wl1;
        erp[1][hloc] += c2 * wr0 + c3 * wr1;
    }
#pragma unroll
    for (int o = 1; o <= 2; o <<= 1) {
#pragma unroll
        for (int i = 0; i < 2; i++) {
#pragma unroll
            for (int hl = 0; hl < 2; hl++) {
                elp[i][hl] += __shfl_xor_sync(0xffffffffu, elp[i][hl], o);
                erp[i][hl] += __shfl_xor_sync(0xffffffffu, erp[i][hl], o);
            }
        }
    }
    if ((lane & 3) == 0) {
        int hbase = wn * 2;
#pragma unroll
        for (int rh = 0; rh < 2; rh++) {
            int n = block_row + wm * 16 + qrow + rh * 8;
            if (n < NN) {
                g_el[n * HH + hbase]     = elp[rh][0];
                g_er[n * HH + hbase]     = erp[rh][0];
                g_el[n * HH + hbase + 1] = elp[rh][1];
                g_er[n * HH + hbase + 1] = erp[rh][1];
            }
        }
    }
}

// ---------------- degree histogram: 4 edges/thread for atomic MLP ----------------
__global__ void hist_kernel(const int* __restrict__ dst) {
    int base = blockIdx.x * 1024 + threadIdx.x;
#pragma unroll
    for (int l = 0; l < 4; l++) {
        int e = base + l * 256;
        if (e < EE) g_rank[e] = atomicAdd(&g_deg[dst[e]], 1);
    }
}

// ---------------- hierarchical scan: 3 small wide kernels ----------------
__global__ void scan1_kernel() {
    __shared__ int sh[256];
    int t = threadIdx.x;
    int idx = blockIdx.x * 256 + t;
    int v = (idx < NN) ? g_deg[idx] : 0;
    sh[t] = v;
    __syncthreads();
#pragma unroll
    for (int d = 1; d < 256; d <<= 1) {
        int a = (t >= d) ? sh[t - d] : 0;
        __syncthreads();
        sh[t] += a;
        __syncthreads();
    }
    if (idx < NN) g_rowstart[idx] = sh[t] - v;
    if (t == 255) g_bsum[blockIdx.x] = sh[255];
}

__global__ void scan2_kernel() {
    __shared__ int sh[256];
    int t = threadIdx.x;
    int v = (t < NSCB) ? g_bsum[t] : 0;
    sh[t] = v;
    __syncthreads();
#pragma unroll
    for (int d = 1; d < 256; d <<= 1) {
        int a = (t >= d) ? sh[t - d] : 0;
        __syncthreads();
        sh[t] += a;
        __syncthreads();
    }
    if (t < NSCB) g_boff[t] = sh[t] - v;
}

__global__ void scan3_kernel() {
    int idx = blockIdx.x * 256 + threadIdx.x;
    if (idx < NN) g_rowstart[idx] += g_boff[blockIdx.x];
    if (idx == 0) g_rowstart[NN] = EE;
}

// ---------------- scatter src ids into CSR order (atomic-free) ----------------
__global__ void sced_kernel(const int* __restrict__ src, const int* __restrict__ dst) {
    int e = blockIdx.x * blockDim.x + threadIdx.x;
    if (e >= EE) return;
    g_srcs[g_rowstart[dst[e]] + g_rank[e]] = src[e];
}

// ---------------- SpMM: dst-centric, fused edge softmax, atomic-free ----------------
__global__ void spmm_kernel(float* __restrict__ out, const float* __restrict__ bias) {
    int n = blockIdx.x;
    int h = threadIdx.x >> 5;
    int lane = threadIdx.x & 31;
    int rs = g_rowstart[n], re = g_rowstart[n + 1];
    int off = h * 32 + lane;
    float er_h = g_er[n * HH + h];
    float acc = 0.f;
    float ssum = 0.f;
    for (int base = rs; base < re; base += 32) {
        int cnt = re - base;
        if (cnt > 32) cnt = 32;
        int sn = 0;
        float av = 0.f;
        if (lane < cnt) {
            sn = g_srcs[base + lane];
            float x = g_el[sn * HH + h] + er_h;
            x = (x > 0.f) ? x : 0.2f * x;
            av = __expf(x);
        }
        for (int j0 = 0; j0 < cnt; j0 += 8) {
#pragma unroll
            for (int jj = 0; jj < 8; jj++) {
                int j = j0 + jj;
                int snj = __shfl_sync(0xffffffffu, sn, j);
                float aj = __shfl_sync(0xffffffffu, av, j);
                acc += g_ft[snj * HD + off] * aj;   // aj==0 past cnt
                ssum += aj;
            }
        }
    }
    float invs = (re > rs) ? (1.0f / ssum) : 0.f;
    out[n * HD + off] = acc * invs + bias[off];
}

// ---------------- launch ----------------
extern "C" void kernel_launch(void* const* d_in, const int* in_sizes, int n_in,
                              void* d_out, int out_size) {
    const float* feat   = (const float*)d_in[0];
    const int*   src    = (const int*)  d_in[1];
    const int*   dst    = (const int*)  d_in[2];
    const float* W      = (const float*)d_in[3];
    const float* attn_l = (const float*)d_in[4];
    const float* attn_r = (const float*)d_in[5];
    const float* bias   = (const float*)d_in[6];
    float* out = (float*)d_out;

    const int smem_bytes = STG_OFF + 2 * STG_SIZE + 1024 + 64;   // ~81KB
    cudaFuncSetAttribute(gemm_kernel, cudaFuncAttributeMaxDynamicSharedMemorySize, smem_bytes);

    setup_kernel<<<NSCB, 256>>>(W);
    hist_kernel<<<(EE + 1023) / 1024, 256>>>(dst);
    scan1_kernel<<<NSCB, 256>>>();
    scan2_kernel<<<1, 256>>>();
    scan3_kernel<<<NSCB, 256>>>();
    gemm_kernel<<<(NN + MTILE - 1) / MTILE, 256, smem_bytes>>>(feat, attn_l, attn_r);
    sced_kernel<<<(EE + 255) / 256, 256>>>(src, dst);
    spmm_kernel<<<NN, 128>>>(out, bias);
}

// round 16
// speedup vs baseline: 1.5672x; 1.0658x over previous
#include <cuda_runtime.h>
#include <cuda_bf16.h>
#include <cstdint>

#define NN 50000
#define EE 800000
#define KF 256          // IN_FEATS
#define HH 4
#define HD 128          // H*D
#define NH 200000       // N*H
#define MTILE 64
#define KC 64           // K chunk
#define NCHUNK (KF / KC)
#define NSCB 196        // scan blocks = ceil(NN/256)

// gemm smem: A bf16 hi/lo (2x8KB) + 2-stage B hi/lo (2x32KB) = 80KB
#define A_HI_OFF 0
#define A_LO_OFF 8192
#define STG_OFF  16384
#define STG_SIZE 32768   // hi 16KB + lo 16KB

// ---------------- scratch (device globals; no allocation) ----------------
__device__ float g_ft[NN * HD];
__device__ float g_el[NH];
__device__ float g_er[NH];
__device__ int   g_srcs[EE];         // src node ids, CSR-sorted by dst
__device__ int   g_deg[NN];
__device__ int   g_rank[EE];         // rank of edge within its dst segment
__device__ int   g_rowstart[NN + 1];
__device__ int   g_bsum[NSCB];
__device__ int   g_boff[NSCB];
__device__ __nv_bfloat16 g_wt_hi[HD * KF];   // W^T split-high  [n][k]
__device__ __nv_bfloat16 g_wt_lo[HD * KF];   // W^T split-low   [n][k]

// ---------------- helpers ----------------
__device__ __forceinline__ uint32_t smem_u32(const void* p) {
    uint32_t a;
    asm("{ .reg .u64 t; cvta.to.shared.u64 t, %1; cvt.u32.u64 %0, t; }" : "=r"(a) : "l"(p));
    return a;
}

#define SW128(o) ((o) ^ (((o) >> 3) & 0x70))

__device__ __forceinline__ void ldm_x4(uint32_t* r, uint32_t addr) {
    asm volatile("ldmatrix.sync.aligned.m8n8.x4.shared.b16 {%0,%1,%2,%3}, [%4];"
                 : "=r"(r[0]), "=r"(r[1]), "=r"(r[2]), "=r"(r[3]) : "r"(addr));
}

__device__ __forceinline__ void mma16816(float* c, const uint32_t* a, const uint32_t* b) {
    asm volatile(
        "mma.sync.aligned.m16n8k16.row.col.f32.bf16.bf16.f32 "
        "{%0,%1,%2,%3}, {%4,%5,%6,%7}, {%8,%9}, {%0,%1,%2,%3};"
        : "+f"(c[0]), "+f"(c[1]), "+f"(c[2]), "+f"(c[3])
        : "r"(a[0]), "r"(a[1]), "r"(a[2]), "r"(a[3]), "r"(b[0]), "r"(b[1]));
}

__device__ __forceinline__ void split_bf16(float x, unsigned short& h, unsigned short& l) {
    __nv_bfloat16 bh = __float2bfloat16(x);
    float r = x - __bfloat162float(bh);
    __nv_bfloat16 bl = __float2bfloat16(r);
    h = __bfloat16_as_ushort(bh);
    l = __bfloat16_as_ushort(bl);
}

// ---------------- CSR chain: zero deg ----------------
__global__ void zerodeg_kernel() {
    int i = blockIdx.x * 256 + threadIdx.x;
    if (i < NN) g_deg[i] = 0;
}

// ---------------- GEMM chain: W transpose + bf16 hi/lo split ----------------
__global__ void wconv_kernel(const float* __restrict__ W) {
    int i = blockIdx.x * 256 + threadIdx.x;
    if (i < HD * KF) {
        int n = i >> 8;
        int k = i & 255;
        float w = W[k * HD + n];
        unsigned short h, l;
        split_bf16(w, h, l);
        g_wt_hi[n * KF + k] = __ushort_as_bfloat16(h);
        g_wt_lo[n * KF + k] = __ushort_as_bfloat16(l);
    }
}

// ---------------- B stage fill via cp.async ----------------
__device__ __forceinline__ void issue_b(int kc, uint32_t stg, int tid) {
#pragma unroll
    for (int l = 0; l < 4; l++) {
        int q = tid + l * 256;              // 0..1023
        int row = q >> 3, c = q & 7;        // n row 0..127, 16B col
        int gidx = row * KF + kc * KC + c * 8;
        uint32_t off = SW128((uint32_t)(row * 128 + c * 16));
        asm volatile("cp.async.cg.shared.global [%0], [%1], 16;"
                     :: "r"(stg + off), "l"(&g_wt_hi[gidx]));
        asm volatile("cp.async.cg.shared.global [%0], [%1], 16;"
                     :: "r"(stg + 16384 + off), "l"(&g_wt_lo[gidx]));
    }
    asm volatile("cp.async.commit_group;" ::: "memory");
}

// ---------------- mma.sync bf16x3 GEMM: m64 CTA, 2 CTA/SM (R12-proven structure) ----------------
__global__ void __launch_bounds__(256, 2) gemm_kernel(const float* __restrict__ A,
                                                      const float* __restrict__ attn_l,
                                                      const float* __restrict__ attn_r) {
    extern __shared__ char smem[];
    const uint32_t sbase = smem_u32(smem);
    const uint32_t ubase = (sbase + 1023) & ~1023u;
    const uint32_t uA_hi = ubase + A_HI_OFF;
    const uint32_t uA_lo = ubase + A_LO_OFF;

    const int tid = threadIdx.x;
    const int wid = tid >> 5;
    const int lane = tid & 31;
    const int wm = wid & 3;        // 4 m groups of 16 rows
    const int wn = wid >> 2;       // 2 n groups of 64 cols
    const int block_row = blockIdx.x * MTILE;

    // prefetch B chunk 0
    issue_b(0, ubase + STG_OFF, tid);

    float acc[8][4];
#pragma unroll
    for (int j = 0; j < 8; j++)
#pragma unroll
        for (int q = 0; q < 4; q++) acc[j][q] = 0.0f;

    const int lrow = (lane & 7) + ((lane >> 3) & 1) * 8;
    const int lkh  = (lane >> 4) * 16;
    const int arow_base = tid >> 4;     // 0..15 (+ l*16 -> 0..63)
    const int ac4 = tid & 15;

    // prefetch A chunk 0 into regs
    float4 a_cur[4];
#pragma unroll
    for (int l = 0; l < 4; l++) {
        int grow = block_row + arow_base + l * 16;
        a_cur[l] = (grow < NN) ? *(const float4*)&A[grow * KF + ac4 * 4]
                               : make_float4(0.f, 0.f, 0.f, 0.f);
    }

    for (int kc = 0; kc < NCHUNK; kc++) {
        // split current A chunk to bf16 hi/lo smem
#pragma unroll
        for (int l = 0; l < 4; l++) {
            int row = arow_base + l * 16;
            float4 v = a_cur[l];
            unsigned short h0, h1, h2, h3, l0, l1, l2, l3;
            split_bf16(v.x, h0, l0); split_bf16(v.y, h1, l1);
            split_bf16(v.z, h2, l2); split_bf16(v.w, h3, l3);
            uint32_t off = SW128((uint32_t)(row * 128 + ac4 * 8));
            *(uint2*)(smem + (uA_hi - sbase) + off) =
                make_uint2(((uint32_t)h1 << 16) | h0, ((uint32_t)h3 << 16) | h2);
            *(uint2*)(smem + (uA_lo - sbase) + off) =
                make_uint2(((uint32_t)l1 << 16) | l0, ((uint32_t)l3 << 16) | l2);
        }
        // prefetch next A chunk (regs free after split; hides under MMA loop)
        if (kc + 1 < NCHUNK) {
#pragma unroll
            for (int l = 0; l < 4; l++) {
                int grow = block_row + arow_base + l * 16;
                a_cur[l] = (grow < NN)
                    ? *(const float4*)&A[grow * KF + (kc + 1) * KC + ac4 * 4]
                    : make_float4(0.f, 0.f, 0.f, 0.f);
            }
            issue_b(kc + 1, ubase + STG_OFF + ((kc + 1) & 1) * STG_SIZE, tid);
            asm volatile("cp.async.wait_group 1;" ::: "memory");
        } else {
            asm volatile("cp.async.wait_group 0;" ::: "memory");
        }
        __syncthreads();

        const uint32_t uB_hi = ubase + STG_OFF + (kc & 1) * STG_SIZE;
        const uint32_t uB_lo = uB_hi + 16384;
#pragma unroll
        for (int ks = 0; ks < 4; ks++) {
            const int kb = ks * 32;

            uint32_t ah[4], al[4];
            int arow = wm * 16 + lrow;
            uint32_t aoff = SW128((uint32_t)(arow * 128 + kb + lkh));
            ldm_x4(ah, uA_hi + aoff);
            ldm_x4(al, uA_lo + aoff);

#pragma unroll
            for (int np = 0; np < 4; np++) {
                int brow = wn * 64 + np * 16 + ((lane >> 4) * 8) + (lane & 7);
                uint32_t boff = SW128((uint32_t)(brow * 128 + kb + (((lane >> 3) & 1) * 16)));
                uint32_t bh[4], bl[4];
                ldm_x4(bh, uB_hi + boff);
                mma16816(acc[np * 2 + 0], ah, bh + 0);
                mma16816(acc[np * 2 + 1], ah, bh + 2);
                mma16816(acc[np * 2 + 0], al, bh + 0);
                mma16816(acc[np * 2 + 1], al, bh + 2);
                ldm_x4(bl, uB_lo + boff);
                mma16816(acc[np * 2 + 0], ah, bl + 0);
                mma16816(acc[np * 2 + 1], ah, bl + 2);
            }
        }
        __syncthreads();
    }

    // --- epilogue: store g_ft + fused el/er ---
    const int qrow = lane >> 2;          // 0..7
    const int qcol = (lane & 3) * 2;
    float elp[2][2], erp[2][2];          // [row-half rh][head-local]
#pragma unroll
    for (int i = 0; i < 2; i++) { elp[i][0] = elp[i][1] = 0.f; erp[i][0] = erp[i][1] = 0.f; }

#pragma unroll
    for (int nt = 0; nt < 8; nt++) {
        int col = wn * 64 + nt * 8 + qcol;
        int hloc = nt >> 2;
        float wl0 = attn_l[col], wl1 = attn_l[col + 1];
        float wr0 = attn_r[col], wr1 = attn_r[col + 1];
        int r0 = block_row + wm * 16 + qrow;
        float c0 = acc[nt][0], c1 = acc[nt][1], c2 = acc[nt][2], c3 = acc[nt][3];
        if (r0 < NN) *(float2*)&g_ft[r0 * HD + col] = make_float2(c0, c1);
        if (r0 + 8 < NN) *(float2*)&g_ft[(r0 + 8) * HD + col] = make_float2(c2, c3);
        elp[0][hloc] += c0 * wl0 + c1 * wl1;
        erp[0][hloc] += c0 * wr0 + c1 * wr1;
        elp[1][hloc] += c2 * wl0 + c3 * wl1;
        erp[1][hloc] += c2 * wr0 + c3 * wr1;
    }
#pragma unroll
    for (int o = 1; o <= 2; o <<= 1) {
#pragma unroll
        for (int i = 0; i < 2; i++) {
#pragma unroll
            for (int hl = 0; hl < 2; hl++) {
                elp[i][hl] += __shfl_xor_sync(0xffffffffu, elp[i][hl], o);
                erp[i][hl] += __shfl_xor_sync(0xffffffffu, erp[i][hl], o);
            }
        }
    }
    if ((lane & 3) == 0) {
        int hbase = wn * 2;
#pragma unroll
        for (int rh = 0; rh < 2; rh++) {
            int n = block_row + wm * 16 + qrow + rh * 8;
            if (n < NN) {
                g_el[n * HH + hbase]     = elp[rh][0];
                g_er[n * HH + hbase]     = erp[rh][0];
                g_el[n * HH + hbase + 1] = elp[rh][1];
                g_er[n * HH + hbase + 1] = erp[rh][1];
            }
        }
    }
}

// ---------------- degree histogram: 4 edges/thread for atomic MLP ----------------
__global__ void hist_kernel(const int* __restrict__ dst) {
    int base = blockIdx.x * 1024 + threadIdx.x;
#pragma unroll
    for (int l = 0; l < 4; l++) {
        int e = base + l * 256;
        if (e < EE) g_rank[e] = atomicAdd(&g_deg[dst[e]], 1);
    }
}

// ---------------- hierarchical scan: 3 small wide kernels ----------------
__global__ void scan1_kernel() {
    __shared__ int sh[256];
    int t = threadIdx.x;
    int idx = blockIdx.x * 256 + t;
    int v = (idx < NN) ? g_deg[idx] : 0;
    sh[t] = v;
    __syncthreads();
#pragma unroll
    for (int d = 1; d < 256; d <<= 1) {
        int a = (t >= d) ? sh[t - d] : 0;
        __syncthreads();
        sh[t] += a;
        __syncthreads();
    }
    if (idx < NN) g_rowstart[idx] = sh[t] - v;
    if (t == 255) g_bsum[blockIdx.x] = sh[255];
}

__global__ void scan2_kernel() {
    __shared__ int sh[256];
    int t = threadIdx.x;
    int v = (t < NSCB) ? g_bsum[t] : 0;
    sh[t] = v;
    __syncthreads();
#pragma unroll
    for (int d = 1; d < 256; d <<= 1) {
        int a = (t >= d) ? sh[t - d] : 0;
        __syncthreads();
        sh[t] += a;
        __syncthreads();
    }
    if (t < NSCB) g_boff[t] = sh[t] - v;
}

__global__ void scan3_kernel() {
    int idx = blockIdx.x * 256 + threadIdx.x;
    if (idx < NN) g_rowstart[idx] += g_boff[blockIdx.x];
    if (idx == 0) g_rowstart[NN] = EE;
}

// ---------------- scatter src ids into CSR order (atomic-free) ----------------
__global__ void sced_kernel(const int* __restrict__ src, const int* __restrict__ dst) {
    int e = blockIdx.x * blockDim.x + threadIdx.x;
    if (e >= EE) return;
    g_srcs[g_rowstart[dst[e]] + g_rank[e]] = src[e];
}

// ---------------- SpMM: dst-centric, fused edge softmax, atomic-free ----------------
__global__ void spmm_kernel(float* __restrict__ out, const float* __restrict__ bias) {
    int n = blockIdx.x;
    int h = threadIdx.x >> 5;
    int lane = threadIdx.x & 31;
    int rs = g_rowstart[n], re = g_rowstart[n + 1];
    int off = h * 32 + lane;
    float er_h = g_er[n * HH + h];
    float acc = 0.f;
    float ssum = 0.f;
    for (int base = rs; base < re; base += 32) {
        int cnt = re - base;
        if (cnt > 32) cnt = 32;
        int sn = 0;
        float av = 0.f;
        if (lane < cnt) {
            sn = g_srcs[base + lane];
            float x = g_el[sn * HH + h] + er_h;
            x = (x > 0.f) ? x : 0.2f * x;
            av = __expf(x);
        }
        for (int j0 = 0; j0 < cnt; j0 += 8) {
#pragma unroll
            for (int jj = 0; jj < 8; jj++) {
                int j = j0 + jj;
                int snj = __shfl_sync(0xffffffffu, sn, j);
                float aj = __shfl_sync(0xffffffffu, av, j);
                acc += g_ft[snj * HD + off] * aj;   // aj==0 past cnt
                ssum += aj;
            }
        }
    }
    float invs = (re > rs) ? (1.0f / ssum) : 0.f;
    out[n * HD + off] = acc * invs + bias[off];
}

// ---------------- launch: fork CSR chain onto a second stream ----------------
extern "C" void kernel_launch(void* const* d_in, const int* in_sizes, int n_in,
                              void* d_out, int out_size) {
    const float* feat   = (const float*)d_in[0];
    const int*   src    = (const int*)  d_in[1];
    const int*   dst    = (const int*)  d_in[2];
    const float* W      = (const float*)d_in[3];
    const float* attn_l = (const float*)d_in[4];
    const float* attn_r = (const float*)d_in[5];
    const float* bias   = (const float*)d_in[6];
    float* out = (float*)d_out;

    static cudaStream_t s2 = nullptr;
    static cudaEvent_t ev_fork = nullptr, ev_join = nullptr;
    if (s2 == nullptr) {
        cudaStreamCreateWithFlags(&s2, cudaStreamNonBlocking);
        cudaEventCreateWithFlags(&ev_fork, cudaEventDisableTiming);
        cudaEventCreateWithFlags(&ev_join, cudaEventDisableTiming);
    }

    const int smem_bytes = STG_OFF + 2 * STG_SIZE + 1024 + 64;   // ~81KB
    cudaFuncSetAttribute(gemm_kernel, cudaFuncAttributeMaxDynamicSharedMemorySize, smem_bytes);

    // fork
    cudaEventRecord(ev_fork, 0);
    cudaStreamWaitEvent(s2, ev_fork, 0);

    // CSR chain (src/dst only) on s2
    zerodeg_kernel<<<NSCB, 256, 0, s2>>>();
    hist_kernel<<<(EE + 1023) / 1024, 256, 0, s2>>>(dst);
    scan1_kernel<<<NSCB, 256, 0, s2>>>();
    scan2_kernel<<<1, 256, 0, s2>>>();
    scan3_kernel<<<NSCB, 256, 0, s2>>>();
    sced_kernel<<<(EE + 255) / 256, 256, 0, s2>>>(src, dst);
    cudaEventRecord(ev_join, s2);

    // GEMM chain (feat/W only) on the capture stream
    wconv_kernel<<<(HD * KF + 255) / 256, 256>>>(W);
    gemm_kernel<<<(NN + MTILE - 1) / MTILE, 256, smem_bytes>>>(feat, attn_l, attn_r);

    // join, then spmm consumes both chains
    cudaStreamWaitEvent(0, ev_join, 0);
    spmm_kernel<<<NN, 128>>>(out, bias);
}